// round 15
// baseline (speedup 1.0000x reference)
#include <cuda_runtime.h>
#include <cuda_bf16.h>
#include <math.h>

#define N_NODES 100864
#define N_EDGES 1613824
#define N_GRAPHS 512
#define IN_C 384
#define HID 128
#define OUT_C 2
#define GEMM_BLOCKS (N_NODES / 128)           // 788

// ---------------- scratch (static __device__, zero-init at load) ----------
__device__ int   g_cnt[N_NODES];        // invariant: zero at entry of every call
__device__ int   g_rowptr[N_NODES + 1];
__device__ int   g_fill[N_NODES];
__device__ int   g_col[N_EDGES];
__device__ __align__(16) float g_dinv[N_NODES];
__device__ __align__(16) float g_bufA[(size_t)N_NODES * HID];  // GEMM out (pre-scaled by dinv[row])
__device__ __align__(16) float g_bufB[(size_t)N_NODES * HID];  // agg out
__device__ __align__(16) float g_pool[N_GRAPHS * HID];
__device__ __align__(16) float g_cntg[N_GRAPHS];

// ---------------- degree count (dst side) ----------------
__global__ void count_kernel(const int* __restrict__ edge) {
    int e = blockIdx.x * blockDim.x + threadIdx.x;
    if (e >= N_EDGES) return;
    unsigned dst = (unsigned)edge[N_EDGES + e];
    if (dst >= N_NODES) dst = 0;
    atomicAdd(&g_cnt[dst], 1);
}

// ------- coalesced tiled block-scan: rowptr, fill, dinv; zero pool/cntg ----
__global__ void scan_kernel() {
    __shared__ int wsum[32];
    __shared__ int carry_s;
    const int t = threadIdx.x;          // 1024 threads
    const int lane = t & 31, wid = t >> 5;
    for (int i = t; i < N_GRAPHS * HID; i += 1024) g_pool[i] = 0.0f;
    for (int i = t; i < N_GRAPHS; i += 1024) g_cntg[i] = 0.0f;
    if (t == 0) carry_s = 0;
    __syncthreads();
    for (int base = 0; base < N_NODES; base += 1024) {
        int i = base + t;
        int c = (i < N_NODES) ? g_cnt[i] : 0;     // coalesced
        int x = c;
        #pragma unroll
        for (int off = 1; off < 32; off <<= 1) {
            int y = __shfl_up_sync(0xFFFFFFFF, x, off);
            if (lane >= off) x += y;
        }
        if (lane == 31) wsum[wid] = x;
        __syncthreads();
        if (wid == 0) {
            int w = wsum[lane];
            #pragma unroll
            for (int off = 1; off < 32; off <<= 1) {
                int y = __shfl_up_sync(0xFFFFFFFF, w, off);
                if (lane >= off) w += y;
            }
            wsum[lane] = w;
        }
        __syncthreads();
        int warpoff = (wid == 0) ? 0 : wsum[wid - 1];
        int excl = carry_s + warpoff + x - c;
        if (i < N_NODES) {
            g_rowptr[i] = excl;
            g_fill[i]   = excl;
            g_dinv[i]   = rsqrtf((float)c + 1.0f); // +1 self-loop
        }
        __syncthreads();
        if (t == 0) carry_s += wsum[31];
        __syncthreads();
    }
    if (t == 0) g_rowptr[N_NODES] = carry_s;
}

// ---------------- CSR fill ----------------
__global__ void fill_kernel(const int* __restrict__ edge) {
    int e = blockIdx.x * blockDim.x + threadIdx.x;
    if (e >= N_EDGES) return;
    unsigned src = (unsigned)edge[e];
    unsigned dst = (unsigned)edge[N_EDGES + e];
    if (src >= N_NODES) src = 0;
    if (dst >= N_NODES) dst = 0;
    int p = atomicAdd(&g_fill[dst], 1);
    g_col[p] = (int)src;
}

// ---------------- tf32 helpers ----------------
__device__ __forceinline__ unsigned to_tf32(float x) {
    unsigned h; asm("cvt.rna.tf32.f32 %0, %1;" : "=r"(h) : "f"(x));
    return h;
}
__device__ __forceinline__ void mma8(float* d, const unsigned* a, const unsigned* b) {
    asm("mma.sync.aligned.m16n8k8.row.col.f32.tf32.tf32.f32 "
        "{%0,%1,%2,%3},{%4,%5,%6,%7},{%8,%9},{%0,%1,%2,%3};"
        : "+f"(d[0]), "+f"(d[1]), "+f"(d[2]), "+f"(d[3])
        : "r"(a[0]), "r"(a[1]), "r"(a[2]), "r"(a[3]), "r"(b[0]), "r"(b[1]));
}

// ---- tensor-core GEMM: C[M,128] = dinv[row] * (A[M,K] @ B[K,128]) ---------
// 1xTF32, block tile 128x128, BK=32, 8 warps (4Mx2N), warp tile 32x64.
// Register prefetch for the next k-tile overlaps LDG latency with mma work.
template<int K>
__device__ __forceinline__ void mma_gemm_body(const float* __restrict__ A,
                                              const float* __restrict__ B,
                                              float* __restrict__ C,
                                              int blockM) {
    __shared__ unsigned As[32][136];   // tf32 bits, [k][m]
    __shared__ unsigned Bs[32][136];   // tf32 bits, [k][n]
    const int tid  = threadIdx.x;
    const int lane = tid & 31;
    const int warp = tid >> 5;
    const int g    = lane >> 2, tig = lane & 3;
    const int warpM = warp >> 1, warpN = warp & 1;
    const int rowBase = blockM * 128;

    float acc[2][8][4];
    #pragma unroll
    for (int mt = 0; mt < 2; mt++)
        #pragma unroll
        for (int nt = 0; nt < 8; nt++)
            #pragma unroll
            for (int i = 0; i < 4; i++) acc[mt][nt][i] = 0.0f;

    const int aRow = tid >> 1, aK = (tid & 1) * 16;
    const int bK = tid >> 3,  bN = (tid & 7) * 16;

    float4 pa[4], pb[4];
    #pragma unroll
    for (int i = 0; i < 4; i++)
        pa[i] = *(const float4*)&A[(size_t)(rowBase + aRow) * K + (aK + i * 4)];
    #pragma unroll
    for (int i = 0; i < 4; i++)
        pb[i] = *(const float4*)&B[(size_t)bK * 128 + bN + i * 4];

    for (int k0 = 0; k0 < K; k0 += 32) {
        #pragma unroll
        for (int i = 0; i < 4; i++) {
            As[aK + i * 4 + 0][aRow] = to_tf32(pa[i].x);
            As[aK + i * 4 + 1][aRow] = to_tf32(pa[i].y);
            As[aK + i * 4 + 2][aRow] = to_tf32(pa[i].z);
            As[aK + i * 4 + 3][aRow] = to_tf32(pa[i].w);
            Bs[bK][bN + i * 4 + 0] = to_tf32(pb[i].x);
            Bs[bK][bN + i * 4 + 1] = to_tf32(pb[i].y);
            Bs[bK][bN + i * 4 + 2] = to_tf32(pb[i].z);
            Bs[bK][bN + i * 4 + 3] = to_tf32(pb[i].w);
        }
        __syncthreads();
        if (k0 + 32 < K) {          // prefetch next tile under compute
            #pragma unroll
            for (int i = 0; i < 4; i++)
                pa[i] = *(const float4*)&A[(size_t)(rowBase + aRow) * K + (k0 + 32 + aK + i * 4)];
            #pragma unroll
            for (int i = 0; i < 4; i++)
                pb[i] = *(const float4*)&B[(size_t)(k0 + 32 + bK) * 128 + bN + i * 4];
        }
        #pragma unroll
        for (int kk = 0; kk < 4; kk++) {
            const int kb = kk * 8;
            unsigned ah[2][4];
            #pragma unroll
            for (int mt = 0; mt < 2; mt++) {
                int r0 = warpM * 32 + mt * 16 + g;
                ah[mt][0] = As[kb + tig    ][r0];
                ah[mt][1] = As[kb + tig    ][r0 + 8];
                ah[mt][2] = As[kb + tig + 4][r0];
                ah[mt][3] = As[kb + tig + 4][r0 + 8];
            }
            #pragma unroll
            for (int nt = 0; nt < 8; nt++) {
                int c0 = warpN * 64 + nt * 8 + g;
                unsigned bh[2];
                bh[0] = Bs[kb + tig    ][c0];
                bh[1] = Bs[kb + tig + 4][c0];
                #pragma unroll
                for (int mt = 0; mt < 2; mt++)
                    mma8(acc[mt][nt], ah[mt], bh);
            }
        }
        __syncthreads();
    }
    // epilogue: scale row r by dinv[r] (pre-normalizes messages for the agg)
    #pragma unroll
    for (int mt = 0; mt < 2; mt++) {
        int r = rowBase + warpM * 32 + mt * 16 + g;
        float d0 = g_dinv[r], d1 = g_dinv[r + 8];
        #pragma unroll
        for (int nt = 0; nt < 8; nt++) {
            int c = warpN * 64 + nt * 8 + tig * 2;
            *(float2*)&C[(size_t)r * 128 + c] =
                make_float2(acc[mt][nt][0] * d0, acc[mt][nt][1] * d0);
            *(float2*)&C[(size_t)(r + 8) * 128 + c] =
                make_float2(acc[mt][nt][2] * d1, acc[mt][nt][3] * d1);
        }
    }
}

__global__ __launch_bounds__(256, 2)
void gemm1_kernel(const float* __restrict__ x, const float* __restrict__ W1) {
    mma_gemm_body<IN_C>(x, W1, g_bufA, blockIdx.x);
}
__global__ __launch_bounds__(256, 2)
void gemm2_kernel(const float* __restrict__ W2) {
    mma_gemm_body<HID>(g_bufB, W2, g_bufA, blockIdx.x);
}

// ------------- aggregation core: shuffle-broadcast idx, 4x-unrolled gather --
__device__ __forceinline__ float4 agg_node(int w, int lane, const float* __restrict__ h) {
    float4 acc = *(const float4*)(h + (size_t)w * HID + lane * 4);  // self term
    int beg = g_rowptr[w], end = g_rowptr[w + 1];
    for (int c0 = beg; c0 < end; c0 += 32) {
        int n = end - c0; if (n > 32) n = 32;
        int myIdx = (lane < n) ? g_col[c0 + lane] : 0;
        int i = 0;
        for (; i + 4 <= n; i += 4) {
            int s0 = __shfl_sync(0xFFFFFFFF, myIdx, i);
            int s1 = __shfl_sync(0xFFFFFFFF, myIdx, i + 1);
            int s2 = __shfl_sync(0xFFFFFFFF, myIdx, i + 2);
            int s3 = __shfl_sync(0xFFFFFFFF, myIdx, i + 3);
            float4 v0 = *(const float4*)(h + (size_t)s0 * HID + lane * 4);
            float4 v1 = *(const float4*)(h + (size_t)s1 * HID + lane * 4);
            float4 v2 = *(const float4*)(h + (size_t)s2 * HID + lane * 4);
            float4 v3 = *(const float4*)(h + (size_t)s3 * HID + lane * 4);
            acc.x += (v0.x + v1.x) + (v2.x + v3.x);
            acc.y += (v0.y + v1.y) + (v2.y + v3.y);
            acc.z += (v0.z + v1.z) + (v2.z + v3.z);
            acc.w += (v0.w + v1.w) + (v2.w + v3.w);
        }
        for (; i < n; i++) {
            int s = __shfl_sync(0xFFFFFFFF, myIdx, i);
            float4 v = *(const float4*)(h + (size_t)s * HID + lane * 4);
            acc.x += v.x; acc.y += v.y; acc.z += v.z; acc.w += v.w;
        }
    }
    return acc;
}

// layer-1 agg -> bufB
__global__ void agg_kernel(const float* __restrict__ bias) {
    int w = (blockIdx.x * blockDim.x + threadIdx.x) >> 5;
    int lane = threadIdx.x & 31;
    if (w >= N_NODES) return;
    float4 acc = agg_node(w, lane, g_bufA);
    float dv = g_dinv[w];
    float4 b = *(const float4*)(bias + lane * 4);
    float4 o;
    o.x = fmaxf(dv * acc.x + b.x, 0.0f);
    o.y = fmaxf(dv * acc.y + b.y, 0.0f);
    o.z = fmaxf(dv * acc.z + b.z, 0.0f);
    o.w = fmaxf(dv * acc.w + b.w, 0.0f);
    *(float4*)(g_bufB + (size_t)w * HID + lane * 4) = o;
}

// layer-2 agg + fused mean-pool
__global__ void agg_pool_kernel(const float* __restrict__ bias,
                                const int* __restrict__ bids) {
    int w = (blockIdx.x * blockDim.x + threadIdx.x) >> 5;
    int lane = threadIdx.x & 31;
    if (w >= N_NODES) return;
    float4 acc = agg_node(w, lane, g_bufA);
    float dv = g_dinv[w];
    float4 b = *(const float4*)(bias + lane * 4);
    float4 o;
    o.x = fmaxf(dv * acc.x + b.x, 0.0f);
    o.y = fmaxf(dv * acc.y + b.y, 0.0f);
    o.z = fmaxf(dv * acc.z + b.z, 0.0f);
    o.w = fmaxf(dv * acc.w + b.w, 0.0f);
    unsigned gr = (unsigned)bids[w];
    if (gr >= N_GRAPHS) gr = 0;
    float* p = &g_pool[gr * HID + lane * 4];
    atomicAdd(p + 0, o.x);
    atomicAdd(p + 1, o.y);
    atomicAdd(p + 2, o.z);
    atomicAdd(p + 3, o.w);
    if (lane == 0) atomicAdd(&g_cntg[gr], 1.0f);
}

// -------- final head: 1 warp/graph; tail re-zeroes g_cnt for next call -----
__global__ void final_kernel(const float* __restrict__ Wlin,
                             const float* __restrict__ blin,
                             float* __restrict__ out) {
    int g = (blockIdx.x * blockDim.x + threadIdx.x) >> 5;
    int lane = threadIdx.x & 31;
    if (g < N_GRAPHS) {
        float inv = 1.0f / fmaxf(g_cntg[g], 1.0f);
        float4 p = *(const float4*)(&g_pool[g * HID + lane * 4]);
        p.x *= inv; p.y *= inv; p.z *= inv; p.w *= inv;
        int c = lane * 4;
        float s0 = p.x * Wlin[c * 2]       + p.y * Wlin[(c + 1) * 2]
                 + p.z * Wlin[(c + 2) * 2] + p.w * Wlin[(c + 3) * 2];
        float s1 = p.x * Wlin[c * 2 + 1]       + p.y * Wlin[(c + 1) * 2 + 1]
                 + p.z * Wlin[(c + 2) * 2 + 1] + p.w * Wlin[(c + 3) * 2 + 1];
        #pragma unroll
        for (int off = 16; off > 0; off >>= 1) {
            s0 += __shfl_xor_sync(0xFFFFFFFF, s0, off);
            s1 += __shfl_xor_sync(0xFFFFFFFF, s1, off);
        }
        if (lane == 0) {
            out[g * 2 + 0] = s0 + blin[0];
            out[g * 2 + 1] = s1 + blin[1];
        }
    }
    int stride = gridDim.x * blockDim.x;
    for (int i = blockIdx.x * blockDim.x + threadIdx.x; i < N_NODES; i += stride)
        g_cnt[i] = 0;
}

// ---------------- launch (all kernels at natural occupancy) -----------------
extern "C" void kernel_launch(void* const* d_in, const int* in_sizes, int n_in,
                              void* d_out, int out_size) {
    const float* x    = (const float*)d_in[0];
    const int*   edge = (const int*)d_in[1];
    const int*   bids = (const int*)d_in[2];
    const float* W1   = (const float*)d_in[3];
    const float* b1   = (const float*)d_in[4];
    const float* W2   = (const float*)d_in[5];
    const float* b2   = (const float*)d_in[6];
    const float* Wlin = (const float*)d_in[7];
    const float* blin = (const float*)d_in[8];
    float*       out  = (float*)d_out;

    int edgeBlocks = (N_EDGES + 255) / 256;
    int aggBlocks  = (N_NODES * 32 + 255) / 256;

    count_kernel<<<edgeBlocks, 256>>>(edge);
    scan_kernel<<<1, 1024>>>();
    fill_kernel<<<edgeBlocks, 256>>>(edge);
    gemm1_kernel<<<GEMM_BLOCKS, 256>>>(x, W1);
    agg_kernel<<<aggBlocks, 256>>>(b1);
    gemm2_kernel<<<GEMM_BLOCKS, 256>>>(W2);
    agg_pool_kernel<<<aggBlocks, 256>>>(b2, bids);
    final_kernel<<<(N_GRAPHS * 32 + 255) / 256, 256>>>(Wlin, blin, out);
}

// round 16
// speedup vs baseline: 1.1929x; 1.1929x over previous
#include <cuda_runtime.h>
#include <cuda_bf16.h>
#include <math.h>

#define N_NODES 100864
#define N_EDGES 1613824
#define N_GRAPHS 512
#define IN_C 384
#define HID 128
#define OUT_C 2
#define GEMM_BLOCKS (N_NODES / 128)           // 788

// ---------------- scratch (static __device__, zero-init at load) ----------
__device__ int   g_cnt[N_NODES];        // invariant: zero at entry of every call
__device__ int   g_rowptr[N_NODES + 1];
__device__ int   g_fill[N_NODES];
__device__ int   g_col[N_EDGES];
__device__ __align__(16) float g_dinv[N_NODES];
__device__ __align__(16) float g_bufA[(size_t)N_NODES * HID];  // GEMM out (pre-scaled by dinv[row])
__device__ __align__(16) float g_bufB[(size_t)N_NODES * HID];  // agg out
__device__ __align__(16) float g_pool[N_GRAPHS * HID];
__device__ __align__(16) float g_cntg[N_GRAPHS];

// ---------------- degree count (dst side) ----------------
__global__ void count_kernel(const int* __restrict__ edge) {
    int e = blockIdx.x * blockDim.x + threadIdx.x;
    if (e >= N_EDGES) return;
    unsigned dst = (unsigned)edge[N_EDGES + e];
    if (dst >= N_NODES) dst = 0;
    atomicAdd(&g_cnt[dst], 1);
}

// ------- coalesced tiled block-scan: rowptr, fill, dinv; zero pool/cntg ----
__global__ void scan_kernel() {
    __shared__ int wsum[32];
    __shared__ int carry_s;
    const int t = threadIdx.x;          // 1024 threads
    const int lane = t & 31, wid = t >> 5;
    for (int i = t; i < N_GRAPHS * HID; i += 1024) g_pool[i] = 0.0f;
    for (int i = t; i < N_GRAPHS; i += 1024) g_cntg[i] = 0.0f;
    if (t == 0) carry_s = 0;
    __syncthreads();
    for (int base = 0; base < N_NODES; base += 1024) {
        int i = base + t;
        int c = (i < N_NODES) ? g_cnt[i] : 0;     // coalesced
        int x = c;
        #pragma unroll
        for (int off = 1; off < 32; off <<= 1) {
            int y = __shfl_up_sync(0xFFFFFFFF, x, off);
            if (lane >= off) x += y;
        }
        if (lane == 31) wsum[wid] = x;
        __syncthreads();
        if (wid == 0) {
            int w = wsum[lane];
            #pragma unroll
            for (int off = 1; off < 32; off <<= 1) {
                int y = __shfl_up_sync(0xFFFFFFFF, w, off);
                if (lane >= off) w += y;
            }
            wsum[lane] = w;
        }
        __syncthreads();
        int warpoff = (wid == 0) ? 0 : wsum[wid - 1];
        int excl = carry_s + warpoff + x - c;
        if (i < N_NODES) {
            g_rowptr[i] = excl;
            g_fill[i]   = excl;
            g_dinv[i]   = rsqrtf((float)c + 1.0f); // +1 self-loop
        }
        __syncthreads();
        if (t == 0) carry_s += wsum[31];
        __syncthreads();
    }
    if (t == 0) g_rowptr[N_NODES] = carry_s;
}

// ---------------- CSR fill ----------------
__global__ void fill_kernel(const int* __restrict__ edge) {
    int e = blockIdx.x * blockDim.x + threadIdx.x;
    if (e >= N_EDGES) return;
    unsigned src = (unsigned)edge[e];
    unsigned dst = (unsigned)edge[N_EDGES + e];
    if (src >= N_NODES) src = 0;
    if (dst >= N_NODES) dst = 0;
    int p = atomicAdd(&g_fill[dst], 1);
    g_col[p] = (int)src;
}

// ---------------- tf32 helpers ----------------
__device__ __forceinline__ unsigned to_tf32(float x) {
    unsigned h; asm("cvt.rna.tf32.f32 %0, %1;" : "=r"(h) : "f"(x));
    return h;
}
__device__ __forceinline__ void mma8(float* d, const unsigned* a, const unsigned* b) {
    asm("mma.sync.aligned.m16n8k8.row.col.f32.tf32.tf32.f32 "
        "{%0,%1,%2,%3},{%4,%5,%6,%7},{%8,%9},{%0,%1,%2,%3};"
        : "+f"(d[0]), "+f"(d[1]), "+f"(d[2]), "+f"(d[3])
        : "r"(a[0]), "r"(a[1]), "r"(a[2]), "r"(a[3]), "r"(b[0]), "r"(b[1]));
}

// ---- tensor-core GEMM: C[M,128] = dinv[row] * (A[M,K] @ B[K,128]) ---------
// 1xTF32, block tile 128x128, BK=32, 8 warps (4Mx2N), warp tile 32x64.
template<int K>
__device__ __forceinline__ void mma_gemm_body(const float* __restrict__ A,
                                              const float* __restrict__ B,
                                              float* __restrict__ C,
                                              int blockM) {
    __shared__ unsigned As[32][136];   // tf32 bits, [k][m]
    __shared__ unsigned Bs[32][136];   // tf32 bits, [k][n]
    const int tid  = threadIdx.x;
    const int lane = tid & 31;
    const int warp = tid >> 5;
    const int g    = lane >> 2, tig = lane & 3;
    const int warpM = warp >> 1, warpN = warp & 1;
    const int rowBase = blockM * 128;

    float acc[2][8][4];
    #pragma unroll
    for (int mt = 0; mt < 2; mt++)
        #pragma unroll
        for (int nt = 0; nt < 8; nt++)
            #pragma unroll
            for (int i = 0; i < 4; i++) acc[mt][nt][i] = 0.0f;

    const int aRow = tid >> 1, aK = (tid & 1) * 16;
    const int bK = tid >> 3,  bN = (tid & 7) * 16;

    float4 pa[4], pb[4];
    #pragma unroll
    for (int i = 0; i < 4; i++)
        pa[i] = *(const float4*)&A[(size_t)(rowBase + aRow) * K + (aK + i * 4)];
    #pragma unroll
    for (int i = 0; i < 4; i++)
        pb[i] = *(const float4*)&B[(size_t)bK * 128 + bN + i * 4];

    for (int k0 = 0; k0 < K; k0 += 32) {
        #pragma unroll
        for (int i = 0; i < 4; i++) {
            As[aK + i * 4 + 0][aRow] = to_tf32(pa[i].x);
            As[aK + i * 4 + 1][aRow] = to_tf32(pa[i].y);
            As[aK + i * 4 + 2][aRow] = to_tf32(pa[i].z);
            As[aK + i * 4 + 3][aRow] = to_tf32(pa[i].w);
            Bs[bK][bN + i * 4 + 0] = to_tf32(pb[i].x);
            Bs[bK][bN + i * 4 + 1] = to_tf32(pb[i].y);
            Bs[bK][bN + i * 4 + 2] = to_tf32(pb[i].z);
            Bs[bK][bN + i * 4 + 3] = to_tf32(pb[i].w);
        }
        __syncthreads();
        if (k0 + 32 < K) {          // prefetch next tile under compute
            #pragma unroll
            for (int i = 0; i < 4; i++)
                pa[i] = *(const float4*)&A[(size_t)(rowBase + aRow) * K + (k0 + 32 + aK + i * 4)];
            #pragma unroll
            for (int i = 0; i < 4; i++)
                pb[i] = *(const float4*)&B[(size_t)(k0 + 32 + bK) * 128 + bN + i * 4];
        }
        #pragma unroll
        for (int kk = 0; kk < 4; kk++) {
            const int kb = kk * 8;
            unsigned ah[2][4];
            #pragma unroll
            for (int mt = 0; mt < 2; mt++) {
                int r0 = warpM * 32 + mt * 16 + g;
                ah[mt][0] = As[kb + tig    ][r0];
                ah[mt][1] = As[kb + tig    ][r0 + 8];
                ah[mt][2] = As[kb + tig + 4][r0];
                ah[mt][3] = As[kb + tig + 4][r0 + 8];
            }
            #pragma unroll
            for (int nt = 0; nt < 8; nt++) {
                int c0 = warpN * 64 + nt * 8 + g;
                unsigned bh[2];
                bh[0] = Bs[kb + tig    ][c0];
                bh[1] = Bs[kb + tig + 4][c0];
                #pragma unroll
                for (int mt = 0; mt < 2; mt++)
                    mma8(acc[mt][nt], ah[mt], bh);
            }
        }
        __syncthreads();
    }
    // epilogue: scale row r by dinv[r] (pre-normalizes messages for the agg)
    #pragma unroll
    for (int mt = 0; mt < 2; mt++) {
        int r = rowBase + warpM * 32 + mt * 16 + g;
        float d0 = g_dinv[r], d1 = g_dinv[r + 8];
        #pragma unroll
        for (int nt = 0; nt < 8; nt++) {
            int c = warpN * 64 + nt * 8 + tig * 2;
            *(float2*)&C[(size_t)r * 128 + c] =
                make_float2(acc[mt][nt][0] * d0, acc[mt][nt][1] * d0);
            *(float2*)&C[(size_t)(r + 8) * 128 + c] =
                make_float2(acc[mt][nt][2] * d1, acc[mt][nt][3] * d1);
        }
    }
}

__global__ __launch_bounds__(256, 2)
void gemm1_kernel(const float* __restrict__ x, const float* __restrict__ W1) {
    mma_gemm_body<IN_C>(x, W1, g_bufA, blockIdx.x);
}
__global__ __launch_bounds__(256, 2)
void gemm2_kernel(const float* __restrict__ W2) {
    mma_gemm_body<HID>(g_bufB, W2, g_bufA, blockIdx.x);
}

// ------------- aggregation core: shuffle-broadcast idx, 4x-unrolled gather --
__device__ __forceinline__ float4 agg_node(int w, int lane, const float* __restrict__ h) {
    float4 acc = *(const float4*)(h + (size_t)w * HID + lane * 4);  // self term
    int beg = g_rowptr[w], end = g_rowptr[w + 1];
    for (int c0 = beg; c0 < end; c0 += 32) {
        int n = end - c0; if (n > 32) n = 32;
        int myIdx = (lane < n) ? g_col[c0 + lane] : 0;
        int i = 0;
        for (; i + 4 <= n; i += 4) {
            int s0 = __shfl_sync(0xFFFFFFFF, myIdx, i);
            int s1 = __shfl_sync(0xFFFFFFFF, myIdx, i + 1);
            int s2 = __shfl_sync(0xFFFFFFFF, myIdx, i + 2);
            int s3 = __shfl_sync(0xFFFFFFFF, myIdx, i + 3);
            float4 v0 = *(const float4*)(h + (size_t)s0 * HID + lane * 4);
            float4 v1 = *(const float4*)(h + (size_t)s1 * HID + lane * 4);
            float4 v2 = *(const float4*)(h + (size_t)s2 * HID + lane * 4);
            float4 v3 = *(const float4*)(h + (size_t)s3 * HID + lane * 4);
            acc.x += (v0.x + v1.x) + (v2.x + v3.x);
            acc.y += (v0.y + v1.y) + (v2.y + v3.y);
            acc.z += (v0.z + v1.z) + (v2.z + v3.z);
            acc.w += (v0.w + v1.w) + (v2.w + v3.w);
        }
        for (; i < n; i++) {
            int s = __shfl_sync(0xFFFFFFFF, myIdx, i);
            float4 v = *(const float4*)(h + (size_t)s * HID + lane * 4);
            acc.x += v.x; acc.y += v.y; acc.z += v.z; acc.w += v.w;
        }
    }
    return acc;
}

// layer-1 agg -> bufB
__global__ void agg_kernel(const float* __restrict__ bias) {
    int w = (blockIdx.x * blockDim.x + threadIdx.x) >> 5;
    int lane = threadIdx.x & 31;
    if (w >= N_NODES) return;
    float4 acc = agg_node(w, lane, g_bufA);
    float dv = g_dinv[w];
    float4 b = *(const float4*)(bias + lane * 4);
    float4 o;
    o.x = fmaxf(dv * acc.x + b.x, 0.0f);
    o.y = fmaxf(dv * acc.y + b.y, 0.0f);
    o.z = fmaxf(dv * acc.z + b.z, 0.0f);
    o.w = fmaxf(dv * acc.w + b.w, 0.0f);
    *(float4*)(g_bufB + (size_t)w * HID + lane * 4) = o;
}

// layer-2 agg + fused mean-pool with BLOCK-SEGMENTED reduction ---------------
// batch_ids is sorted, so the 8 nodes of a block almost always share a graph:
// reduce across warps in SMEM and emit 128 atomics per block instead of 1024.
__global__ void agg_pool_kernel(const float* __restrict__ bias,
                                const int* __restrict__ bids) {
    __shared__ float4 sh[8][32];
    __shared__ int shgr[8];
    int warp = threadIdx.x >> 5;
    int lane = threadIdx.x & 31;
    int w = blockIdx.x * 8 + warp;          // N_NODES = 12608*8, always valid
    float4 acc = agg_node(w, lane, g_bufA);
    float dv = g_dinv[w];
    float4 b = *(const float4*)(bias + lane * 4);
    float4 o;
    o.x = fmaxf(dv * acc.x + b.x, 0.0f);
    o.y = fmaxf(dv * acc.y + b.y, 0.0f);
    o.z = fmaxf(dv * acc.z + b.z, 0.0f);
    o.w = fmaxf(dv * acc.w + b.w, 0.0f);
    unsigned gr = (unsigned)bids[w];
    if (gr >= N_GRAPHS) gr = 0;
    sh[warp][lane] = o;
    if (lane == 0) shgr[warp] = (int)gr;
    __syncthreads();
    int g0 = shgr[0];
    bool uni = true;
    #pragma unroll
    for (int i = 1; i < 8; i++) uni &= (shgr[i] == g0);
    if (uni) {
        if (threadIdx.x < HID) {
            int c = threadIdx.x;
            float s = 0.0f;
            #pragma unroll
            for (int i = 0; i < 8; i++) {
                const float* p = (const float*)&sh[i][c >> 2];
                s += p[c & 3];
            }
            atomicAdd(&g_pool[g0 * HID + c], s);
        }
        if (threadIdx.x == HID) atomicAdd(&g_cntg[g0], 8.0f);
    } else {
        float* p = &g_pool[gr * HID + lane * 4];
        atomicAdd(p + 0, o.x);
        atomicAdd(p + 1, o.y);
        atomicAdd(p + 2, o.z);
        atomicAdd(p + 3, o.w);
        if (lane == 0) atomicAdd(&g_cntg[gr], 1.0f);
    }
}

// -------- final head: 1 warp/graph; tail re-zeroes g_cnt for next call -----
__global__ void final_kernel(const float* __restrict__ Wlin,
                             const float* __restrict__ blin,
                             float* __restrict__ out) {
    int g = (blockIdx.x * blockDim.x + threadIdx.x) >> 5;
    int lane = threadIdx.x & 31;
    if (g < N_GRAPHS) {
        float inv = 1.0f / fmaxf(g_cntg[g], 1.0f);
        float4 p = *(const float4*)(&g_pool[g * HID + lane * 4]);
        p.x *= inv; p.y *= inv; p.z *= inv; p.w *= inv;
        int c = lane * 4;
        float s0 = p.x * Wlin[c * 2]       + p.y * Wlin[(c + 1) * 2]
                 + p.z * Wlin[(c + 2) * 2] + p.w * Wlin[(c + 3) * 2];
        float s1 = p.x * Wlin[c * 2 + 1]       + p.y * Wlin[(c + 1) * 2 + 1]
                 + p.z * Wlin[(c + 2) * 2 + 1] + p.w * Wlin[(c + 3) * 2 + 1];
        #pragma unroll
        for (int off = 16; off > 0; off >>= 1) {
            s0 += __shfl_xor_sync(0xFFFFFFFF, s0, off);
            s1 += __shfl_xor_sync(0xFFFFFFFF, s1, off);
        }
        if (lane == 0) {
            out[g * 2 + 0] = s0 + blin[0];
            out[g * 2 + 1] = s1 + blin[1];
        }
    }
    int stride = gridDim.x * blockDim.x;
    for (int i = blockIdx.x * blockDim.x + threadIdx.x; i < N_NODES; i += stride)
        g_cnt[i] = 0;
}

// ---------------- launch ----------------------------------------------------
extern "C" void kernel_launch(void* const* d_in, const int* in_sizes, int n_in,
                              void* d_out, int out_size) {
    const float* x    = (const float*)d_in[0];
    const int*   edge = (const int*)d_in[1];
    const int*   bids = (const int*)d_in[2];
    const float* W1   = (const float*)d_in[3];
    const float* b1   = (const float*)d_in[4];
    const float* W2   = (const float*)d_in[5];
    const float* b2   = (const float*)d_in[6];
    const float* Wlin = (const float*)d_in[7];
    const float* blin = (const float*)d_in[8];
    float*       out  = (float*)d_out;

    int edgeBlocks = (N_EDGES + 255) / 256;
    int aggBlocks  = (N_NODES * 32 + 255) / 256;

    count_kernel<<<edgeBlocks, 256>>>(edge);
    scan_kernel<<<1, 1024>>>();
    fill_kernel<<<edgeBlocks, 256>>>(edge);
    gemm1_kernel<<<GEMM_BLOCKS, 256>>>(x, W1);
    agg_kernel<<<aggBlocks, 256>>>(b1);
    gemm2_kernel<<<GEMM_BLOCKS, 256>>>(W2);
    agg_pool_kernel<<<aggBlocks, 256>>>(b2, bids);
    final_kernel<<<(N_GRAPHS * 32 + 255) / 256, 256>>>(Wlin, blin, out);
}